// round 7
// baseline (speedup 1.0000x reference)
#include <cuda_runtime.h>
#include <cstdint>

#define BATCH 4096
#define DIM   768
#define NEXP  16
#define KD    1536
#define KSEL  50
#define NPAIR (BATCH*2)

// ---------------- f32x2 packed-math macros ----------------
#define FMA2(d,a,b) asm("fma.rn.f32x2 %0, %1, %2, %3;" : "=l"(d) : "l"(a), "l"(b), "l"(d))
#define PACK2(d,lo,hi) asm("mov.b64 %0, {%1, %2};" : "=l"(d) : "f"(lo), "f"(hi))
#define UNPACK2(lo,hi,v) asm("mov.b64 {%0, %1}, %2;" : "=f"(lo), "=f"(hi) : "l"(v))
typedef unsigned long long u64;

// ---------------- device scratch ----------------
__device__ float g_F[NPAIR * KD];       // masked relu activations, 50.3 MB
__device__ float g_w[NPAIR];            // gate weight per (token,slot)
__device__ int   g_route[NPAIR];        // expert id per (token,slot)
__device__ int   g_cnt[NEXP];
__device__ int   g_list[NEXP * BATCH];

// ---------------- init ----------------
__global__ void k_init() {
    if (threadIdx.x < NEXP) g_cnt[threadIdx.x] = 0;
}

// ---------------- gate + route: one warp per token ----------------
__global__ void __launch_bounds__(128) k_gate(const float* __restrict__ x,
                                              const float* __restrict__ Wg,
                                              const float* __restrict__ bg,
                                              const float* __restrict__ b_gate) {
    int b = blockIdx.x * 4 + (threadIdx.x >> 5);
    int lane = threadIdx.x & 31;
    const float* xr = x + (size_t)b * DIM;

    float pe[NEXP];
#pragma unroll
    for (int e = 0; e < NEXP; e++) pe[e] = 0.f;
    for (int d = lane; d < DIM; d += 32) {
        float xv = xr[d] - b_gate[d];
#pragma unroll
        for (int e = 0; e < NEXP; e++) pe[e] += xv * Wg[e * DIM + d];
    }
#pragma unroll
    for (int e = 0; e < NEXP; e++) {
#pragma unroll
        for (int o = 16; o > 0; o >>= 1) pe[e] += __shfl_xor_sync(0xffffffffu, pe[e], o);
        pe[e] += bg[e];
    }
    float m = pe[0];
#pragma unroll
    for (int e = 1; e < NEXP; e++) m = fmaxf(m, pe[e]);
    float s = 0.f;
#pragma unroll
    for (int e = 0; e < NEXP; e++) { pe[e] = expf(pe[e] - m); s += pe[e]; }
    float inv = 1.f / s;
    float v1 = -1.f, v2 = -1.f; int i1 = 0, i2 = 0;
#pragma unroll
    for (int e = 0; e < NEXP; e++) {
        float p = pe[e] * inv;
        if (p > v1)      { v2 = v1; i2 = i1; v1 = p; i1 = e; }
        else if (p > v2) { v2 = p;  i2 = e; }
    }
    float e1 = expf(v1), e2 = expf(v2);
    float w0 = e1 / (e1 + e2), w1 = e2 / (e1 + e2);

    if (lane == 0) {
        int p0 = b * 2, p1 = b * 2 + 1;
        g_route[p0] = i1; g_route[p1] = i2;
        g_w[p0] = w0;     g_w[p1] = w1;
        int q0 = atomicAdd(&g_cnt[i1], 1); g_list[i1 * BATCH + q0] = p0;
        int q1 = atomicAdd(&g_cnt[i2], 1); g_list[i2 * BATCH + q1] = p1;
    }
}

// ---------------- grouped encode GEMM (f32x2, A pre-duplicated in smem) ----------------
// tile 128(M pairs) x 128(N dict), K-chunks of 8, 256 threads, 8x8 microtile
#define TM 128
#define TN 128
#define TK 8
#define LDP 132   // Ws padded row stride (floats)
#define LDU 130   // XsD padded row stride (u64)

struct __align__(16) SmemEnc {
    u64   XsD[2][TK][LDU];   // duplicated-pair A values
    float Ws[2][TK][LDP];
    int   pair[TM];
};

__global__ void __launch_bounds__(256, 2) k_encode(const float* __restrict__ x,
                                                   const float* __restrict__ b_dec,
                                                   const float* __restrict__ Wenc,
                                                   const float* __restrict__ benc) {
    __shared__ SmemEnc sm;
    int e  = blockIdx.y >> 5;
    int mt = blockIdx.y & 31;
    int cnt = g_cnt[e];
    int m0 = mt * TM;
    if (m0 >= cnt) return;
    int n0 = blockIdx.x * TN;

    int tid = threadIdx.x;
    if (tid < TM) {
        int m = m0 + tid;
        sm.pair[tid] = (m < cnt) ? g_list[e * BATCH + m] : -1;
    }
    __syncthreads();

    int tx = tid & 15, ty = tid >> 4;

    u64 acc[8][4];
#pragma unroll
    for (int i = 0; i < 8; i++)
#pragma unroll
        for (int j = 0; j < 4; j++) acc[i][j] = 0ULL;

    // loader mapping: thread -> one float4 of X and one of W per chunk
    int lr = tid >> 1;            // 0..127
    int kc = (tid & 1) * 4;       // 0 or 4
    int pairL = sm.pair[lr];
    int tokenL = (pairL >= 0 ? pairL : 0) >> 1;
    const float* xrow = x + (size_t)tokenL * DIM + kc;
    const float* wrow = Wenc + (size_t)e * KD * DIM + (size_t)(n0 + lr) * DIM + kc;
    const float* brow = b_dec + kc;

    float4 nx = *(const float4*)(xrow);
    float4 nb = *(const float4*)(brow);
    float4 nw = *(const float4*)(wrow);
    nx.x -= nb.x; nx.y -= nb.y; nx.z -= nb.z; nx.w -= nb.w;
    {
        u64 d0, d1, d2, d3;
        PACK2(d0, nx.x, nx.x); PACK2(d1, nx.y, nx.y);
        PACK2(d2, nx.z, nx.z); PACK2(d3, nx.w, nx.w);
        sm.XsD[0][kc + 0][lr] = d0; sm.XsD[0][kc + 1][lr] = d1;
        sm.XsD[0][kc + 2][lr] = d2; sm.XsD[0][kc + 3][lr] = d3;
    }
    sm.Ws[0][kc + 0][lr] = nw.x; sm.Ws[0][kc + 1][lr] = nw.y;
    sm.Ws[0][kc + 2][lr] = nw.z; sm.Ws[0][kc + 3][lr] = nw.w;
    __syncthreads();

    int buf = 0;
#pragma unroll 1
    for (int c = 1; c < DIM / TK; c++) {
        nx = *(const float4*)(xrow + c * TK);
        nb = *(const float4*)(brow + c * TK);
        nw = *(const float4*)(wrow + c * TK);
        nx.x -= nb.x; nx.y -= nb.y; nx.z -= nb.z; nx.w -= nb.w;
#pragma unroll
        for (int kk = 0; kk < TK; kk++) {
            const u64* xp = &sm.XsD[buf][kk][ty * 8];
            ulonglong2 A01 = *(const ulonglong2*)(xp);
            ulonglong2 A23 = *(const ulonglong2*)(xp + 2);
            ulonglong2 A45 = *(const ulonglong2*)(xp + 4);
            ulonglong2 A67 = *(const ulonglong2*)(xp + 6);
            ulonglong2 b0 = *(const ulonglong2*)&sm.Ws[buf][kk][tx * 8];
            ulonglong2 b1 = *(const ulonglong2*)&sm.Ws[buf][kk][tx * 8 + 4];
            u64 av[8] = {A01.x, A01.y, A23.x, A23.y, A45.x, A45.y, A67.x, A67.y};
#pragma unroll
            for (int i = 0; i < 8; i++) {
                FMA2(acc[i][0], av[i], b0.x);
                FMA2(acc[i][1], av[i], b0.y);
                FMA2(acc[i][2], av[i], b1.x);
                FMA2(acc[i][3], av[i], b1.y);
            }
        }
        int nbuf = buf ^ 1;
        {
            u64 d0, d1, d2, d3;
            PACK2(d0, nx.x, nx.x); PACK2(d1, nx.y, nx.y);
            PACK2(d2, nx.z, nx.z); PACK2(d3, nx.w, nx.w);
            sm.XsD[nbuf][kc + 0][lr] = d0; sm.XsD[nbuf][kc + 1][lr] = d1;
            sm.XsD[nbuf][kc + 2][lr] = d2; sm.XsD[nbuf][kc + 3][lr] = d3;
        }
        sm.Ws[nbuf][kc + 0][lr] = nw.x; sm.Ws[nbuf][kc + 1][lr] = nw.y;
        sm.Ws[nbuf][kc + 2][lr] = nw.z; sm.Ws[nbuf][kc + 3][lr] = nw.w;
        __syncthreads();
        buf = nbuf;
    }
    // last chunk
#pragma unroll
    for (int kk = 0; kk < TK; kk++) {
        const u64* xp = &sm.XsD[buf][kk][ty * 8];
        ulonglong2 A01 = *(const ulonglong2*)(xp);
        ulonglong2 A23 = *(const ulonglong2*)(xp + 2);
        ulonglong2 A45 = *(const ulonglong2*)(xp + 4);
        ulonglong2 A67 = *(const ulonglong2*)(xp + 6);
        ulonglong2 b0 = *(const ulonglong2*)&sm.Ws[buf][kk][tx * 8];
        ulonglong2 b1 = *(const ulonglong2*)&sm.Ws[buf][kk][tx * 8 + 4];
        u64 av[8] = {A01.x, A01.y, A23.x, A23.y, A45.x, A45.y, A67.x, A67.y};
#pragma unroll
        for (int i = 0; i < 8; i++) {
            FMA2(acc[i][0], av[i], b0.x);
            FMA2(acc[i][1], av[i], b0.y);
            FMA2(acc[i][2], av[i], b1.x);
            FMA2(acc[i][3], av[i], b1.y);
        }
    }

    // epilogue: bias + relu + gate-weight, store to g_F
    const float* be = benc + (size_t)e * KD + n0 + tx * 8;
    float4 bl = *(const float4*)(be);
    float4 bh = *(const float4*)(be + 4);
#pragma unroll
    for (int i = 0; i < 8; i++) {
        int m = ty * 8 + i;
        int pair = sm.pair[m];
        if (pair < 0) continue;
        float w = g_w[pair];
        float c0, c1, c2, c3, c4, c5, c6, c7;
        UNPACK2(c0, c1, acc[i][0]);
        UNPACK2(c2, c3, acc[i][1]);
        UNPACK2(c4, c5, acc[i][2]);
        UNPACK2(c6, c7, acc[i][3]);
        float4 r0, r1;
        r0.x = fmaxf(c0 + bl.x, 0.f) * w; r0.y = fmaxf(c1 + bl.y, 0.f) * w;
        r0.z = fmaxf(c2 + bl.z, 0.f) * w; r0.w = fmaxf(c3 + bl.w, 0.f) * w;
        r1.x = fmaxf(c4 + bh.x, 0.f) * w; r1.y = fmaxf(c5 + bh.y, 0.f) * w;
        r1.z = fmaxf(c6 + bh.z, 0.f) * w; r1.w = fmaxf(c7 + bh.w, 0.f) * w;
        float* dst = g_F + (size_t)pair * KD + n0 + tx * 8;
        *(float4*)(dst)     = r0;
        *(float4*)(dst + 4) = r1;
    }
}

// ---------------- decode: histogram radix top-50 + vectorized gather ----------------
__global__ void __launch_bounds__(192) k_decode(const float* __restrict__ b_dec,
                                                const float* __restrict__ Wdec,
                                                float* __restrict__ out) {
    int b = blockIdx.x;
    int tid = threadIdx.x;
    int lane = tid & 31;
    int wid = tid >> 5;

    __shared__ float    sf[KD];
    __shared__ unsigned cand[KD];
    __shared__ int      hist[256];
    __shared__ int      sel[64];
    __shared__ int      s_nsel, s_m, s_E, s_k2, s_special;
    __shared__ unsigned s_thr;

    float4 bd = *(const float4*)(b_dec + tid * 4);
    u64 acc01, acc23;
    PACK2(acc01, bd.x, bd.y);
    PACK2(acc23, bd.z, bd.w);

    for (int slot = 0; slot < 2; slot++) {
        int pair = b * 2 + slot;
        int e = g_route[pair];
        const float* Fr = g_F + (size_t)pair * KD;

        // reset hist + counters; load values
        for (int i = tid; i < 256; i += 192) hist[i] = 0;
        if (tid == 0) s_m = 0;
        unsigned rv[8];
#pragma unroll
        for (int j = 0; j < 8; j++) {
            float v = Fr[tid + 192 * j];
            sf[tid + 192 * j] = v;
            rv[j] = __float_as_uint(v);
        }
        __syncthreads();

        // exponent histogram (nonzero values only; f >= 0 so sign bit clear)
#pragma unroll
        for (int j = 0; j < 8; j++)
            if (rv[j]) atomicAdd(&hist[rv[j] >> 23], 1);
        __syncthreads();

        // warp 0: cooperative top-down scan -> boundary exponent bin E, residual k2
        if (wid == 0) {
            int base = 255 - 8 * lane;        // lane 0 covers top bins 248..255
            int c[8], cl = 0;
#pragma unroll
            for (int j = 0; j < 8; j++) { c[j] = hist[base - j]; cl += c[j]; }
            // inclusive scan over lanes (lane order = descending bins)
            int incl = cl;
#pragma unroll
            for (int o = 1; o < 32; o <<= 1) {
                int t = __shfl_up_sync(0xffffffffu, incl, o);
                if (lane >= o) incl += t;
            }
            int pre = incl - cl;
            int total = __shfl_sync(0xffffffffu, incl, 31);
            if (total < KSEL) {
                if (lane == 0) { s_special = 1; s_thr = 1u; }
            } else {
                bool owns = (pre < KSEL) && (incl >= KSEL);
                unsigned om = __ballot_sync(0xffffffffu, owns);
                int ol = __ffs(om) - 1;
                int Ev = 0, cumAbove = 0;
                if (owns) {
                    int cum = pre;
#pragma unroll
                    for (int j = 0; j < 8; j++) {
                        if (cum + c[j] >= KSEL) { Ev = base - j; cumAbove = cum; break; }
                        cum += c[j];
                    }
                }
                Ev = __shfl_sync(0xffffffffu, Ev, ol);
                cumAbove = __shfl_sync(0xffffffffu, cumAbove, ol);
                if (lane == 0) {
                    s_special = 0;
                    s_E = Ev;
                    s_k2 = KSEL - cumAbove;
                }
            }
        }
        __syncthreads();

        if (!s_special) {
            int Eall = s_E;
            // collect bin-E candidates
#pragma unroll
            for (int j = 0; j < 8; j++)
                if (rv[j] && (int)(rv[j] >> 23) == Eall) {
                    int p = atomicAdd(&s_m, 1);
                    cand[p] = rv[j];
                }
            __syncthreads();
            // warp 0: mantissa radix descent (no block barriers)
            if (wid == 0) {
                int m = s_m, k2 = s_k2;
                unsigned tm = 0;
                unsigned Ebits = (unsigned)Eall << 23;
#pragma unroll 1
                for (int bit = 22; bit >= 0; bit--) {
                    unsigned t = Ebits | tm | (1u << bit);
                    int cnt = 0;
                    for (int i = lane; i < m; i += 32) cnt += (cand[i] >= t);
#pragma unroll
                    for (int o = 16; o; o >>= 1) cnt += __shfl_xor_sync(0xffffffffu, cnt, o);
                    if (cnt >= k2) tm |= (1u << bit);
                }
                if (lane == 0) s_thr = Ebits | tm;
            }
            __syncthreads();
        }
        unsigned thr = s_thr;

        // order-preserving compaction by warp 0 (exclude exact zeros, cap KSEL)
        if (tid < 32) {
            int ns = 0;
            for (int base = 0; base < KD; base += 32) {
                unsigned bits = __float_as_uint(sf[base + tid]);
                bool p = (bits >= thr) && (bits != 0u);
                unsigned msk = __ballot_sync(0xffffffffu, p);
                int pos = ns + __popc(msk & ((1u << tid) - 1u));
                if (p && pos < KSEL) sel[pos] = base + tid;
                ns += __popc(msk);
            }
            if (tid == 0) s_nsel = (ns < KSEL ? ns : KSEL);
        }
        __syncthreads();
        int nsel = s_nsel;

        // gather-accumulate, 4-row unroll for MLP
        const float* Wd = Wdec + (size_t)e * KD * DIM + tid * 4;
        int i = 0;
        for (; i + 4 <= nsel; i += 4) {
            int k0 = sel[i], k1 = sel[i + 1], k2i = sel[i + 2], k3 = sel[i + 3];
            float f0 = sf[k0], f1 = sf[k1], f2 = sf[k2i], f3 = sf[k3];
            float4 w0 = *(const float4*)(Wd + (size_t)k0 * DIM);
            float4 w1 = *(const float4*)(Wd + (size_t)k1 * DIM);
            float4 w2 = *(const float4*)(Wd + (size_t)k2i * DIM);
            float4 w3 = *(const float4*)(Wd + (size_t)k3 * DIM);
            u64 fp, t;
            PACK2(fp, f0, f0);
            PACK2(t, w0.x, w0.y); FMA2(acc01, fp, t);
            PACK2(t, w0.z, w0.w); FMA2(acc23, fp, t);
            PACK2(fp, f1, f1);
            PACK2(t, w1.x, w1.y); FMA2(acc01, fp, t);
            PACK2(t, w1.z, w1.w); FMA2(acc23, fp, t);
            PACK2(fp, f2, f2);
            PACK2(t, w2.x, w2.y); FMA2(acc01, fp, t);
            PACK2(t, w2.z, w2.w); FMA2(acc23, fp, t);
            PACK2(fp, f3, f3);
            PACK2(t, w3.x, w3.y); FMA2(acc01, fp, t);
            PACK2(t, w3.z, w3.w); FMA2(acc23, fp, t);
        }
        for (; i < nsel; i++) {
            int k0 = sel[i];
            float f0 = sf[k0];
            float4 w0 = *(const float4*)(Wd + (size_t)k0 * DIM);
            u64 fp, t;
            PACK2(fp, f0, f0);
            PACK2(t, w0.x, w0.y); FMA2(acc01, fp, t);
            PACK2(t, w0.z, w0.w); FMA2(acc23, fp, t);
        }
        __syncthreads();   // before sf/cand are overwritten for next slot
    }

    float4 r;
    UNPACK2(r.x, r.y, acc01);
    UNPACK2(r.z, r.w, acc23);
    *(float4*)(out + (size_t)b * DIM + tid * 4) = r;
}

// ---------------- launch ----------------
extern "C" void kernel_launch(void* const* d_in, const int* in_sizes, int n_in,
                              void* d_out, int out_size) {
    const float* x      = (const float*)d_in[0];
    const float* Wg     = (const float*)d_in[1];
    const float* bg     = (const float*)d_in[2];
    const float* b_gate = (const float*)d_in[3];
    const float* b_dec  = (const float*)d_in[4];
    const float* Wenc   = (const float*)d_in[5];
    const float* benc   = (const float*)d_in[6];
    const float* Wdec   = (const float*)d_in[7];
    float* out = (float*)d_out;

    k_init<<<1, 32>>>();
    k_gate<<<BATCH / 4, 128>>>(x, Wg, bg, b_gate);
    k_encode<<<dim3(KD / TN, NEXP * 32), 256>>>(x, b_dec, Wenc, benc);
    k_decode<<<BATCH, 192>>>(b_dec, Wdec, out);
}

// round 8
// speedup vs baseline: 1.1921x; 1.1921x over previous
#include <cuda_runtime.h>
#include <cstdint>

#define BATCH 4096
#define DIM   768
#define NEXP  16
#define KD    1536
#define KSEL  50
#define NPAIR (BATCH*2)

// ---------------- f32x2 packed-math macros ----------------
#define FMA2(d,a,b) asm("fma.rn.f32x2 %0, %1, %2, %3;" : "=l"(d) : "l"(a), "l"(b), "l"(d))
#define PACK2(d,lo,hi) asm("mov.b64 %0, {%1, %2};" : "=l"(d) : "f"(lo), "f"(hi))
#define UNPACK2(lo,hi,v) asm("mov.b64 {%0, %1}, %2;" : "=f"(lo), "=f"(hi) : "l"(v))
typedef unsigned long long u64;

// ---------------- device scratch ----------------
__device__ float g_F[NPAIR * KD];       // masked relu activations, 50.3 MB
__device__ float g_w[NPAIR];            // gate weight per (token,slot)
__device__ int   g_route[NPAIR];        // expert id per (token,slot)
__device__ int   g_cnt[NEXP];
__device__ int   g_list[NEXP * BATCH];

// ---------------- init ----------------
__global__ void k_init() {
    if (threadIdx.x < NEXP) g_cnt[threadIdx.x] = 0;
}

// ---------------- gate + route: one warp per token ----------------
__global__ void __launch_bounds__(128) k_gate(const float* __restrict__ x,
                                              const float* __restrict__ Wg,
                                              const float* __restrict__ bg,
                                              const float* __restrict__ b_gate) {
    int b = blockIdx.x * 4 + (threadIdx.x >> 5);
    int lane = threadIdx.x & 31;
    const float* xr = x + (size_t)b * DIM;

    float pe[NEXP];
#pragma unroll
    for (int e = 0; e < NEXP; e++) pe[e] = 0.f;
    for (int d = lane; d < DIM; d += 32) {
        float xv = xr[d] - b_gate[d];
#pragma unroll
        for (int e = 0; e < NEXP; e++) pe[e] += xv * Wg[e * DIM + d];
    }
#pragma unroll
    for (int e = 0; e < NEXP; e++) {
#pragma unroll
        for (int o = 16; o > 0; o >>= 1) pe[e] += __shfl_xor_sync(0xffffffffu, pe[e], o);
        pe[e] += bg[e];
    }
    float m = pe[0];
#pragma unroll
    for (int e = 1; e < NEXP; e++) m = fmaxf(m, pe[e]);
    float s = 0.f;
#pragma unroll
    for (int e = 0; e < NEXP; e++) { pe[e] = expf(pe[e] - m); s += pe[e]; }
    float inv = 1.f / s;
    float v1 = -1.f, v2 = -1.f; int i1 = 0, i2 = 0;
#pragma unroll
    for (int e = 0; e < NEXP; e++) {
        float p = pe[e] * inv;
        if (p > v1)      { v2 = v1; i2 = i1; v1 = p; i1 = e; }
        else if (p > v2) { v2 = p;  i2 = e; }
    }
    float e1 = expf(v1), e2 = expf(v2);
    float w0 = e1 / (e1 + e2), w1 = e2 / (e1 + e2);

    if (lane == 0) {
        int p0 = b * 2, p1 = b * 2 + 1;
        g_route[p0] = i1; g_route[p1] = i2;
        g_w[p0] = w0;     g_w[p1] = w1;
        int q0 = atomicAdd(&g_cnt[i1], 1); g_list[i1 * BATCH + q0] = p0;
        int q1 = atomicAdd(&g_cnt[i2], 1); g_list[i2 * BATCH + q1] = p1;
    }
}

// ---------------- grouped encode GEMM (f32x2, TK=16) ----------------
// tile 128(M pairs) x 128(N dict), K-chunks of 16, 256 threads, 8x8 microtile
#define TM 128
#define TN 128
#define TK 16
#define LDP 132   // padded row stride (floats)

struct __align__(16) SmemEnc {
    float Xs[2][TK][LDP];
    float Ws[2][TK][LDP];
    int   pair[TM];
};

__global__ void __launch_bounds__(256, 2) k_encode(const float* __restrict__ x,
                                                   const float* __restrict__ b_dec,
                                                   const float* __restrict__ Wenc,
                                                   const float* __restrict__ benc) {
    __shared__ SmemEnc sm;
    int e  = blockIdx.y >> 5;
    int mt = blockIdx.y & 31;
    int cnt = g_cnt[e];
    int m0 = mt * TM;
    if (m0 >= cnt) return;
    int n0 = blockIdx.x * TN;

    int tid = threadIdx.x;
    if (tid < TM) {
        int m = m0 + tid;
        sm.pair[tid] = (m < cnt) ? g_list[e * BATCH + m] : -1;
    }
    __syncthreads();

    int tx = tid & 15, ty = tid >> 4;

    u64 acc[8][4];
#pragma unroll
    for (int i = 0; i < 8; i++)
#pragma unroll
        for (int j = 0; j < 4; j++) acc[i][j] = 0ULL;

    // loader mapping: thread -> two float4 of X and two of W per chunk
    int lr  = tid >> 1;            // 0..127
    int kc0 = (tid & 1) * 8;       // 0 or 8
    int pairL = sm.pair[lr];
    int tokenL = (pairL >= 0 ? pairL : 0) >> 1;
    const float* xrow = x + (size_t)tokenL * DIM + kc0;
    const float* wrow = Wenc + (size_t)e * KD * DIM + (size_t)(n0 + lr) * DIM + kc0;
    const float* brow = b_dec + kc0;

    float4 nxA = *(const float4*)(xrow);
    float4 nxB = *(const float4*)(xrow + 4);
    float4 nbA = *(const float4*)(brow);
    float4 nbB = *(const float4*)(brow + 4);
    float4 nwA = *(const float4*)(wrow);
    float4 nwB = *(const float4*)(wrow + 4);
    nxA.x -= nbA.x; nxA.y -= nbA.y; nxA.z -= nbA.z; nxA.w -= nbA.w;
    nxB.x -= nbB.x; nxB.y -= nbB.y; nxB.z -= nbB.z; nxB.w -= nbB.w;
    sm.Xs[0][kc0 + 0][lr] = nxA.x; sm.Xs[0][kc0 + 1][lr] = nxA.y;
    sm.Xs[0][kc0 + 2][lr] = nxA.z; sm.Xs[0][kc0 + 3][lr] = nxA.w;
    sm.Xs[0][kc0 + 4][lr] = nxB.x; sm.Xs[0][kc0 + 5][lr] = nxB.y;
    sm.Xs[0][kc0 + 6][lr] = nxB.z; sm.Xs[0][kc0 + 7][lr] = nxB.w;
    sm.Ws[0][kc0 + 0][lr] = nwA.x; sm.Ws[0][kc0 + 1][lr] = nwA.y;
    sm.Ws[0][kc0 + 2][lr] = nwA.z; sm.Ws[0][kc0 + 3][lr] = nwA.w;
    sm.Ws[0][kc0 + 4][lr] = nwB.x; sm.Ws[0][kc0 + 5][lr] = nwB.y;
    sm.Ws[0][kc0 + 6][lr] = nwB.z; sm.Ws[0][kc0 + 7][lr] = nwB.w;
    __syncthreads();

    int buf = 0;
#pragma unroll 1
    for (int c = 1; c < DIM / TK; c++) {
        nxA = *(const float4*)(xrow + c * TK);
        nxB = *(const float4*)(xrow + c * TK + 4);
        nbA = *(const float4*)(brow + c * TK);
        nbB = *(const float4*)(brow + c * TK + 4);
        nwA = *(const float4*)(wrow + c * TK);
        nwB = *(const float4*)(wrow + c * TK + 4);
        nxA.x -= nbA.x; nxA.y -= nbA.y; nxA.z -= nbA.z; nxA.w -= nbA.w;
        nxB.x -= nbB.x; nxB.y -= nbB.y; nxB.z -= nbB.z; nxB.w -= nbB.w;
#pragma unroll
        for (int kk = 0; kk < TK; kk++) {
            float4 a0 = *(const float4*)&sm.Xs[buf][kk][ty * 8];
            float4 a1 = *(const float4*)&sm.Xs[buf][kk][ty * 8 + 4];
            ulonglong2 b0 = *(const ulonglong2*)&sm.Ws[buf][kk][tx * 8];
            ulonglong2 b1 = *(const ulonglong2*)&sm.Ws[buf][kk][tx * 8 + 4];
            float av[8] = {a0.x, a0.y, a0.z, a0.w, a1.x, a1.y, a1.z, a1.w};
#pragma unroll
            for (int i = 0; i < 8; i++) {
                u64 ad; PACK2(ad, av[i], av[i]);
                FMA2(acc[i][0], ad, b0.x);
                FMA2(acc[i][1], ad, b0.y);
                FMA2(acc[i][2], ad, b1.x);
                FMA2(acc[i][3], ad, b1.y);
            }
        }
        int nbuf = buf ^ 1;
        sm.Xs[nbuf][kc0 + 0][lr] = nxA.x; sm.Xs[nbuf][kc0 + 1][lr] = nxA.y;
        sm.Xs[nbuf][kc0 + 2][lr] = nxA.z; sm.Xs[nbuf][kc0 + 3][lr] = nxA.w;
        sm.Xs[nbuf][kc0 + 4][lr] = nxB.x; sm.Xs[nbuf][kc0 + 5][lr] = nxB.y;
        sm.Xs[nbuf][kc0 + 6][lr] = nxB.z; sm.Xs[nbuf][kc0 + 7][lr] = nxB.w;
        sm.Ws[nbuf][kc0 + 0][lr] = nwA.x; sm.Ws[nbuf][kc0 + 1][lr] = nwA.y;
        sm.Ws[nbuf][kc0 + 2][lr] = nwA.z; sm.Ws[nbuf][kc0 + 3][lr] = nwA.w;
        sm.Ws[nbuf][kc0 + 4][lr] = nwB.x; sm.Ws[nbuf][kc0 + 5][lr] = nwB.y;
        sm.Ws[nbuf][kc0 + 6][lr] = nwB.z; sm.Ws[nbuf][kc0 + 7][lr] = nwB.w;
        __syncthreads();
        buf = nbuf;
    }
    // last chunk
#pragma unroll
    for (int kk = 0; kk < TK; kk++) {
        float4 a0 = *(const float4*)&sm.Xs[buf][kk][ty * 8];
        float4 a1 = *(const float4*)&sm.Xs[buf][kk][ty * 8 + 4];
        ulonglong2 b0 = *(const ulonglong2*)&sm.Ws[buf][kk][tx * 8];
        ulonglong2 b1 = *(const ulonglong2*)&sm.Ws[buf][kk][tx * 8 + 4];
        float av[8] = {a0.x, a0.y, a0.z, a0.w, a1.x, a1.y, a1.z, a1.w};
#pragma unroll
        for (int i = 0; i < 8; i++) {
            u64 ad; PACK2(ad, av[i], av[i]);
            FMA2(acc[i][0], ad, b0.x);
            FMA2(acc[i][1], ad, b0.y);
            FMA2(acc[i][2], ad, b1.x);
            FMA2(acc[i][3], ad, b1.y);
        }
    }

    // epilogue: bias + relu + gate-weight, store to g_F
    const float* be = benc + (size_t)e * KD + n0 + tx * 8;
    float4 bl = *(const float4*)(be);
    float4 bh = *(const float4*)(be + 4);
#pragma unroll
    for (int i = 0; i < 8; i++) {
        int m = ty * 8 + i;
        int pair = sm.pair[m];
        if (pair < 0) continue;
        float w = g_w[pair];
        float c0, c1, c2, c3, c4, c5, c6, c7;
        UNPACK2(c0, c1, acc[i][0]);
        UNPACK2(c2, c3, acc[i][1]);
        UNPACK2(c4, c5, acc[i][2]);
        UNPACK2(c6, c7, acc[i][3]);
        float4 r0, r1;
        r0.x = fmaxf(c0 + bl.x, 0.f) * w; r0.y = fmaxf(c1 + bl.y, 0.f) * w;
        r0.z = fmaxf(c2 + bl.z, 0.f) * w; r0.w = fmaxf(c3 + bl.w, 0.f) * w;
        r1.x = fmaxf(c4 + bh.x, 0.f) * w; r1.y = fmaxf(c5 + bh.y, 0.f) * w;
        r1.z = fmaxf(c6 + bh.z, 0.f) * w; r1.w = fmaxf(c7 + bh.w, 0.f) * w;
        float* dst = g_F + (size_t)pair * KD + n0 + tx * 8;
        *(float4*)(dst)     = r0;
        *(float4*)(dst + 4) = r1;
    }
}

// ---------------- decode: hist + 1-barrier-per-iter radix top-50 ----------------
__global__ void __launch_bounds__(192) k_decode(const float* __restrict__ b_dec,
                                                const float* __restrict__ Wdec,
                                                float* __restrict__ out) {
    int b = blockIdx.x;
    int tid = threadIdx.x;
    int lane = tid & 31;
    int wid = tid >> 5;

    __shared__ float    sf[KD];
    __shared__ int      hist[256];
    __shared__ int      cntS[23];
    __shared__ int      sel[56];
    __shared__ int      s_nsel, s_E, s_special;

    float4 bd = *(const float4*)(b_dec + tid * 4);
    u64 acc01, acc23;
    PACK2(acc01, bd.x, bd.y);
    PACK2(acc23, bd.z, bd.w);

    for (int slot = 0; slot < 2; slot++) {
        int pair = b * 2 + slot;
        int e = g_route[pair];
        const float* Fr = g_F + (size_t)pair * KD;

        // zero hist + counters; load values
        for (int i = tid; i < 256; i += 192) hist[i] = 0;
        if (tid < 23) cntS[tid] = 0;
        unsigned rv[8];
#pragma unroll
        for (int j = 0; j < 8; j++) {
            float v = Fr[tid + 192 * j];
            sf[tid + 192 * j] = v;
            rv[j] = __float_as_uint(v);
        }
        __syncthreads();                                 // B1

        // exponent histogram (nonzero only; f >= 0)
#pragma unroll
        for (int j = 0; j < 8; j++)
            if (rv[j]) atomicAdd(&hist[rv[j] >> 23], 1);
        __syncthreads();                                 // B2

        // warp 0: find boundary exponent bin E (or special: < KSEL nonzero)
        if (wid == 0) {
            int base = 255 - 8 * lane;        // lane 0 covers top bins 248..255
            int c[8], cl = 0;
#pragma unroll
            for (int j = 0; j < 8; j++) { c[j] = hist[base - j]; cl += c[j]; }
            int incl = cl;
#pragma unroll
            for (int o = 1; o < 32; o <<= 1) {
                int t = __shfl_up_sync(0xffffffffu, incl, o);
                if (lane >= o) incl += t;
            }
            int pre = incl - cl;
            int total = __shfl_sync(0xffffffffu, incl, 31);
            if (total < KSEL) {
                if (lane == 0) s_special = 1;
            } else {
                bool owns = (pre < KSEL) && (incl >= KSEL);
                unsigned om = __ballot_sync(0xffffffffu, owns);
                int ol = __ffs(om) - 1;
                int Ev = 0;
                if (owns) {
                    int cum = pre;
#pragma unroll
                    for (int j = 0; j < 8; j++) {
                        if (cum + c[j] >= KSEL) { Ev = base - j; break; }
                        cum += c[j];
                    }
                }
                Ev = __shfl_sync(0xffffffffu, Ev, ol);
                if (lane == 0) { s_special = 0; s_E = Ev; }
            }
        }
        __syncthreads();                                 // B3

        unsigned thr;
        if (!s_special) {
            unsigned lo = (unsigned)s_E << 23;
#pragma unroll 1
            for (int it = 0; it < 23; it++) {
                int bit = 22 - it;
                unsigned t = lo | (1u << bit);
                int c = 0;
#pragma unroll
                for (int j = 0; j < 8; j++) c += (rv[j] >= t);
                c = __reduce_add_sync(0xffffffffu, c);
                if (lane == 0) atomicAdd(&cntS[it], c);
                __syncthreads();                         // B4..B26
                if (cntS[it] >= KSEL) lo |= (1u << bit);
            }
            thr = lo;       // identical in every thread
        } else {
            thr = 1u;       // select all nonzero
        }

        // order-preserving compaction by warp 0 (exclude exact zeros, cap KSEL)
        if (tid < 32) {
            int ns = 0;
            for (int base = 0; base < KD; base += 32) {
                unsigned bits = __float_as_uint(sf[base + tid]);
                bool p = (bits >= thr) && (bits != 0u);
                unsigned msk = __ballot_sync(0xffffffffu, p);
                int pos = ns + __popc(msk & ((1u << tid) - 1u));
                if (p && pos < KSEL) sel[pos] = base + tid;
                ns += __popc(msk);
            }
            if (tid == 0) s_nsel = (ns < KSEL ? ns : KSEL);
        }
        __syncthreads();                                 // B27
        int nsel = s_nsel;

        // gather-accumulate, 4-row unroll for MLP
        const float* Wd = Wdec + (size_t)e * KD * DIM + tid * 4;
        int i = 0;
        for (; i + 4 <= nsel; i += 4) {
            int k0 = sel[i], k1 = sel[i + 1], k2 = sel[i + 2], k3 = sel[i + 3];
            float f0 = sf[k0], f1 = sf[k1], f2 = sf[k2], f3 = sf[k3];
            float4 w0 = *(const float4*)(Wd + (size_t)k0 * DIM);
            float4 w1 = *(const float4*)(Wd + (size_t)k1 * DIM);
            float4 w2 = *(const float4*)(Wd + (size_t)k2 * DIM);
            float4 w3 = *(const float4*)(Wd + (size_t)k3 * DIM);
            u64 fp, t;
            PACK2(fp, f0, f0);
            PACK2(t, w0.x, w0.y); FMA2(acc01, fp, t);
            PACK2(t, w0.z, w0.w); FMA2(acc23, fp, t);
            PACK2(fp, f1, f1);
            PACK2(t, w1.x, w1.y); FMA2(acc01, fp, t);
            PACK2(t, w1.z, w1.w); FMA2(acc23, fp, t);
            PACK2(fp, f2, f2);
            PACK2(t, w2.x, w2.y); FMA2(acc01, fp, t);
            PACK2(t, w2.z, w2.w); FMA2(acc23, fp, t);
            PACK2(fp, f3, f3);
            PACK2(t, w3.x, w3.y); FMA2(acc01, fp, t);
            PACK2(t, w3.z, w3.w); FMA2(acc23, fp, t);
        }
        for (; i < nsel; i++) {
            int k0 = sel[i];
            float f0 = sf[k0];
            float4 w0 = *(const float4*)(Wd + (size_t)k0 * DIM);
            u64 fp, t;
            PACK2(fp, f0, f0);
            PACK2(t, w0.x, w0.y); FMA2(acc01, fp, t);
            PACK2(t, w0.z, w0.w); FMA2(acc23, fp, t);
        }
        __syncthreads();                                 // B28: before reuse of smem
    }

    float4 r;
    UNPACK2(r.x, r.y, acc01);
    UNPACK2(r.z, r.w, acc23);
    *(float4*)(out + (size_t)b * DIM + tid * 4) = r;
}

// ---------------- launch ----------------
extern "C" void kernel_launch(void* const* d_in, const int* in_sizes, int n_in,
                              void* d_out, int out_size) {
    const float* x      = (const float*)d_in[0];
    const float* Wg     = (const float*)d_in[1];
    const float* bg     = (const float*)d_in[2];
    const float* b_gate = (const float*)d_in[3];
    const float* b_dec  = (const float*)d_in[4];
    const float* Wenc   = (const float*)d_in[5];
    const float* benc   = (const float*)d_in[6];
    const float* Wdec   = (const float*)d_in[7];
    float* out = (float*)d_out;

    k_init<<<1, 32>>>();
    k_gate<<<BATCH / 4, 128>>>(x, Wg, bg, b_gate);
    k_encode<<<dim3(KD / TN, NEXP * 32), 256>>>(x, b_dec, Wenc, benc);
    k_decode<<<BATCH, 192>>>(b_dec, Wdec, out);
}